// round 15
// baseline (speedup 1.0000x reference)
#include <cuda_runtime.h>
#include <cuda_fp16.h>
#include <math.h>
#include <stdint.h>

// ===========================================================================
// SwinV2 block. GEMMs via mma.sync (HMMA) pure fp16 x fp16, fp32 accum.
// CTA 128x128, BK=32, 16 warps of 32x32 (512 thr), 4-stage cp.async,
// 2 CTAs/SM (64 regs/thread target) -> 32 warps/SM.
// QKV intermediate fp16. Attention dots use fma.rn.f32x2 (FFMA2).
// ===========================================================================

#define LN100 4.6051701859880914f

// ------------------------- scratch (device globals) ------------------------
__device__ __align__(128) __half g_xg[33554432];     // [32768][1024] A qkv
__device__ __align__(128) __half g_w2[12582912];     // weights fp16
__device__ __align__(128) __half g_qkvh[100663296];  // [3][512][16][64][64] fp16
__device__ __align__(128) __half g_attn2[33554432];  // [32768][1024] A proj
__device__ __align__(128) __half g_out2[33554432];   // [32768][1024] A fc1
__device__ __align__(128) __half g_h2[134217728];    // [32768][4096] A fc2
__device__ __align__(128) float g_proj[33554432];
__device__ __align__(128) float g_mlp[33554432];
__device__ float g_tbl[3600];

#define W2_QKV  0
#define W2_PROJ 3145728
#define W2_FC1  4194304
#define W2_FC2  8388608

__device__ __forceinline__ int winmap(int wr) {
    int wt = wr >> 6, t = wr & 63;
    int img = wt >> 2, wi = wt & 3;
    int r = (((wi >> 1) << 3) + (t >> 3) + 4) & 15;
    int c = (((wi & 1) << 3) + (t & 7) + 4) & 15;
    return (img << 8) + (r << 4) + c;
}

// ---------------------------- PTX helpers -----------------------------------
__device__ __forceinline__ uint32_t smem_u32(const void* p) {
    uint32_t a;
    asm("{ .reg .u64 t; cvta.to.shared.u64 t, %1; cvt.u32.u64 %0, t; }"
        : "=r"(a) : "l"(p));
    return a;
}
__device__ __forceinline__ void cp16(uint32_t s, const void* g) {
    asm volatile("cp.async.cg.shared.global [%0], [%1], 16;" :: "r"(s), "l"(g));
}
#define CP_COMMIT() asm volatile("cp.async.commit_group;" ::: "memory")
#define CP_WAIT2()  asm volatile("cp.async.wait_group 2;" ::: "memory")

__device__ __forceinline__ void ldmx4(uint32_t a, uint32_t& r0, uint32_t& r1,
                                      uint32_t& r2, uint32_t& r3) {
    asm volatile("ldmatrix.sync.aligned.m8n8.x4.shared.b16 {%0,%1,%2,%3}, [%4];"
                 : "=r"(r0), "=r"(r1), "=r"(r2), "=r"(r3) : "r"(a));
}
__device__ __forceinline__ void mma16816(float* c, const uint32_t* a,
                                         const uint32_t* b) {
    asm volatile(
        "mma.sync.aligned.m16n8k16.row.col.f32.f16.f16.f32 "
        "{%0,%1,%2,%3}, {%4,%5,%6,%7}, {%8,%9}, {%0,%1,%2,%3};"
        : "+f"(c[0]), "+f"(c[1]), "+f"(c[2]), "+f"(c[3])
        : "r"(a[0]), "r"(a[1]), "r"(a[2]), "r"(a[3]), "r"(b[0]), "r"(b[1]));
}
__device__ __forceinline__ void fma2(unsigned long long& c,
                                     unsigned long long a, unsigned long long b) {
    asm("fma.rn.f32x2 %0, %1, %2, %0;" : "+l"(c) : "l"(a), "l"(b));
}
__device__ __forceinline__ float fma2_sum(unsigned long long c) {
    float lo, hi;
    asm("mov.b64 {%0, %1}, %2;" : "=f"(lo), "=f"(hi) : "l"(c));
    return lo + hi;
}

// ------------------------------- HMMA GEMM ----------------------------------
// C[M,N] = A[M,K] * B[N,K]^T. CTA 128x128, BK=32, 16 warps of 32x32.
// MODE 0: QKV scatter (+q/v bias) -> g_qkvh fp16
// MODE 1: +bias -> Cf fp32
// MODE 2: +bias +exact GELU -> g_h2 fp16
// MODE 3: +bias -> Cf fp32
#define SPITCH 80
#define ATILE  10240           // 128*80
#define STAGEB 20480           // A + B

template <int MODE>
__global__ void __launch_bounds__(512, 2) mma_gemm(
    const __half* __restrict__ A, const __half* __restrict__ B,
    const float* __restrict__ bias, const float* __restrict__ bias2,
    float* __restrict__ Cf, int K, int N)
{
    extern __shared__ __align__(128) char sm[];
    const uint32_t smu = smem_u32(sm);
    const int tid = threadIdx.x;
    const int lane = tid & 31, w = tid >> 5;
    const int warpM = w >> 2, warpN = w & 3;     // 4 x 4 warps, 32x32 tiles
    const int row0 = blockIdx.y * 128, col0 = blockIdx.x * 128;

    // ---- cp.async: tid<256 loads A rows, tid>=256 loads B rows -------------
    const int hsel = tid >> 8;                   // 0: A, 1: B
    const int r1 = (tid & 255) >> 1;             // 0..127
    const int kc2 = (tid & 1) * 2;               // chunk pair 0-1 or 2-3
    const __half* Gp = (hsel ? (B + (size_t)(col0 + r1) * K)
                             : (A + (size_t)(row0 + r1) * K)) + kc2 * 8;
    const uint32_t sd = (uint32_t)(hsel * ATILE + r1 * SPITCH + kc2 * 16);

    // ---- ldmatrix lane offsets (within stage) ----
    const uint32_t aoff =
        (uint32_t)((warpM * 32 + (lane & 7) + ((lane >> 3) & 1) * 8) * SPITCH +
                   ((lane >> 4) & 1) * 16);
    const uint32_t boff =
        (uint32_t)(ATILE + (warpN * 32 + (lane & 7) + ((lane >> 4) & 1) * 8) * SPITCH +
                   ((lane >> 3) & 1) * 16);

    float acc[8][4];
#pragma unroll
    for (int i = 0; i < 8; i++)
#pragma unroll
        for (int j = 0; j < 4; j++) acc[i][j] = 0.f;

    const int T = K >> 5;

    // prologue: stages 0,1,2
#pragma unroll
    for (int s = 0; s < 3; s++) {
        const uint32_t sb = smu + s * STAGEB;
        const size_t ko = (size_t)s * 32;
        cp16(sb + sd,      Gp + ko);
        cp16(sb + sd + 16, Gp + ko + 8);
        CP_COMMIT();
    }

    for (int kt = 0; kt < T; ++kt) {
        CP_WAIT2();
        __syncthreads();

        if (kt + 3 < T) {
            const uint32_t sb = smu + ((kt + 3) & 3) * STAGEB;
            const size_t ko = (size_t)(kt + 3) * 32;
            cp16(sb + sd,      Gp + ko);
            cp16(sb + sd + 16, Gp + ko + 8);
        }
        CP_COMMIT();

        const uint32_t base = smu + (kt & 3) * STAGEB;
#pragma unroll
        for (int kk = 0; kk < 2; kk++) {
            uint32_t bf[4][2];
#pragma unroll
            for (int p = 0; p < 2; p++)
                ldmx4(base + boff + p * 16 * SPITCH + kk * 32,
                      bf[2 * p][0], bf[2 * p][1], bf[2 * p + 1][0], bf[2 * p + 1][1]);
#pragma unroll
            for (int mt = 0; mt < 2; mt++) {
                uint32_t af[4];
                ldmx4(base + aoff + mt * 16 * SPITCH + kk * 32,
                      af[0], af[1], af[2], af[3]);
#pragma unroll
                for (int nt = 0; nt < 4; nt++)
                    mma16816(acc[mt * 4 + nt], af, bf[nt]);
            }
        }
    }

    // ------------------------------ epilogue --------------------------------
#pragma unroll
    for (int mt = 0; mt < 2; mt++) {
#pragma unroll
        for (int nt = 0; nt < 4; nt++) {
            const float* c = acc[mt * 4 + nt];
            const int col = col0 + warpN * 32 + nt * 8 + (lane & 3) * 2;
#pragma unroll
            for (int half = 0; half < 2; half++) {
                const int row = row0 + warpM * 32 + mt * 16 + (lane >> 2) + half * 8;
                const float v0 = c[half * 2 + 0], v1 = c[half * 2 + 1];
                if (MODE == 0) {
                    const int which = col >> 10, rem = col & 1023;
                    const float* bs = (which == 0) ? bias : (which == 2) ? bias2 : nullptr;
                    const float b0 = bs ? bs[rem] : 0.f, b1 = bs ? bs[rem + 1] : 0.f;
                    __half* dst = g_qkvh + (size_t)which * 33554432 +
                                  (size_t)(row >> 6) * 65536 + (rem >> 6) * 4096 +
                                  (row & 63) * 64 + (rem & 63);
                    __half2 hh;
                    hh.x = __float2half_rn(v0 + b0);
                    hh.y = __float2half_rn(v1 + b1);
                    *(__half2*)dst = hh;
                } else if (MODE == 2) {
                    float s0 = v0 + bias[col], s1 = v1 + bias[col + 1];
                    s0 = 0.5f * s0 * (1.0f + erff(s0 * 0.70710678118654752f));
                    s1 = 0.5f * s1 * (1.0f + erff(s1 * 0.70710678118654752f));
                    __half2 hh;
                    hh.x = __float2half_rn(s0);
                    hh.y = __float2half_rn(s1);
                    *(__half2*)(g_h2 + (size_t)row * 4096 + col) = hh;
                } else {
                    float* dst = Cf + (size_t)row * N + col;
                    *(float2*)dst = make_float2(v0 + bias[col], v1 + bias[col + 1]);
                }
            }
        }
    }
}

// ------------------------- convert / gather kernels --------------------------
__global__ void __launch_bounds__(256) xconv_kernel(const float* __restrict__ x)
{
    const int wr = blockIdx.x;
    const int g = winmap(wr);
    const float4 v = *(const float4*)(x + (size_t)g * 1024 + threadIdx.x * 4);
    __half2 h01, h23;
    h01.x = __float2half_rn(v.x); h01.y = __float2half_rn(v.y);
    h23.x = __float2half_rn(v.z); h23.y = __float2half_rn(v.w);
    __half* dst = g_xg + (size_t)wr * 1024 + threadIdx.x * 4;
    *(__half2*)(dst) = h01;
    *(__half2*)(dst + 2) = h23;
}

__global__ void __launch_bounds__(256) wconv_kernel(
    const float* __restrict__ src, __half* __restrict__ dst, int K)
{
    const int row = blockIdx.x;
    const float* s = src + (size_t)row * K;
    __half* d = dst + (size_t)row * K;
    for (int c = threadIdx.x * 4; c < K; c += 1024) {
        const float4 v = *(const float4*)(s + c);
        __half2 h01, h23;
        h01.x = __float2half_rn(v.x); h01.y = __float2half_rn(v.y);
        h23.x = __float2half_rn(v.z); h23.y = __float2half_rn(v.w);
        *(__half2*)(d + c) = h01;
        *(__half2*)(d + c + 2) = h23;
    }
}

// --------------------------- CPB bias table ---------------------------------
__global__ void cpb_kernel(const float* __restrict__ w1,
                           const float* __restrict__ b1,
                           const float* __restrict__ w2)
{
    __shared__ float hbuf[512];
    const int p = blockIdx.x;
    const int a = p / 15, b = p % 15;
    const float va = (a - 7) * (1.0f / 7.0f), vb = (b - 7) * (1.0f / 7.0f);
    const float c0 = (va > 0.f ? 1.f : (va < 0.f ? -1.f : 0.f)) * log2f(1.f + fabsf(va));
    const float c1 = (vb > 0.f ? 1.f : (vb < 0.f ? -1.f : 0.f)) * log2f(1.f + fabsf(vb));
    const int j = threadIdx.x;
    float hv = w1[j * 2] * c0 + w1[j * 2 + 1] * c1 + b1[j];
    hbuf[j] = fmaxf(hv, 0.f);
    __syncthreads();
    if (j < 16) {
        float s = 0.f;
        for (int t = 0; t < 512; t++) s += hbuf[t] * w2[j * 512 + t];
        g_tbl[p * 16 + j] = 16.f / (1.f + expf(-s));
    }
}

// ------------------------------ attention -----------------------------------
__global__ void __launch_bounds__(256) attn_kernel(const float* __restrict__ ls)
{
    __shared__ float sA[64 * 68];
    __shared__ float sB[64 * 66];
    __shared__ float rn[128];

    const int h = blockIdx.x, wt = blockIdx.y;
    const int tid = threadIdx.x;
    const __half* qg = g_qkvh + (size_t)wt * 65536 + h * 4096;
    const __half* kg = qg + 33554432;
    const __half* vg = qg + 67108864;

#pragma unroll
    for (int i = 0; i < 2; i++) {
        const int idx = tid + 256 * i;
        const int r = idx >> 3, c8 = (idx & 7) * 8;
        uint4 rawq = *(const uint4*)(qg + (size_t)r * 64 + c8);
        uint4 rawk = *(const uint4*)(kg + (size_t)r * 64 + c8);
        const __half2* hq = (const __half2*)&rawq;
        const __half2* hk = (const __half2*)&rawk;
#pragma unroll
        for (int j = 0; j < 4; j++) {
            float2 fq = __half22float2(hq[j]);
            float2 fk = __half22float2(hk[j]);
            sA[r * 68 + c8 + 2 * j]     = fq.x;
            sA[r * 68 + c8 + 2 * j + 1] = fq.y;
            sB[r * 66 + c8 + 2 * j]     = fk.x;
            sB[r * 66 + c8 + 2 * j + 1] = fk.y;
        }
    }
    __syncthreads();

    {
        const int r = tid >> 2, part = tid & 3;
        float sq = 0.f, sk = 0.f;
#pragma unroll
        for (int j = 0; j < 16; j++) {
            float xq = sA[r * 68 + part + 4 * j]; sq += xq * xq;
            float xk = sB[r * 66 + part + 4 * j]; sk += xk * xk;
        }
        sq += __shfl_xor_sync(0xffffffffu, sq, 1);
        sq += __shfl_xor_sync(0xffffffffu, sq, 2);
        sk += __shfl_xor_sync(0xffffffffu, sk, 1);
        sk += __shfl_xor_sync(0xffffffffu, sk, 2);
        if (part == 0) {
            rn[r]      = 1.f / fmaxf(sqrtf(sq), 1e-12f);
            rn[64 + r] = 1.f / fmaxf(sqrtf(sk), 1e-12f);
        }
    }
    __syncthreads();

    const float scale = expf(fminf(ls[h], LN100));
    const int wi = wt & 3;
    const int m = tid & 63;
    const int nbase = tid >> 6;

    unsigned long long kreg2[32];
#pragma unroll
    for (int kk = 0; kk < 32; kk++)
        kreg2[kk] = *(const unsigned long long*)&sB[m * 66 + 2 * kk];

    const int srm = ((wi >> 1) << 3) + (m >> 3), scm = ((wi & 1) << 3) + (m & 7);
    const int rgm = (srm < 8 ? 0 : (srm < 12 ? 1 : 2)) * 3 +
                    (scm < 8 ? 0 : (scm < 12 ? 1 : 2));

    float sc[16];
#pragma unroll
    for (int i = 0; i < 16; i++) {
        const int n = nbase + 4 * i;
        unsigned long long acc2 = 0ULL;
        const unsigned long long* qp = (const unsigned long long*)&sA[n * 68];
#pragma unroll
        for (int k2 = 0; k2 < 32; k2++) fma2(acc2, qp[k2], kreg2[k2]);
        float dot = fma2_sum(acc2);
        dot *= rn[n] * rn[64 + m] * scale;
        const int idx = ((n >> 3) - (m >> 3) + 7) * 15 + ((n & 7) - (m & 7) + 7);
        dot += g_tbl[idx * 16 + h];
        const int srn = ((wi >> 1) << 3) + (n >> 3), scn = ((wi & 1) << 3) + (n & 7);
        const int rgn = (srn < 8 ? 0 : (srn < 12 ? 1 : 2)) * 3 +
                        (scn < 8 ? 0 : (scn < 12 ? 1 : 2));
        if (rgn != rgm) dot -= 100.f;
        sc[i] = dot;
    }
    __syncthreads();

#pragma unroll
    for (int i = 0; i < 16; i++) sA[(nbase + 4 * i) * 68 + m] = sc[i];
#pragma unroll
    for (int i = 0; i < 2; i++) {
        const int idx = tid + 256 * i;
        const int r = idx >> 3, c8 = (idx & 7) * 8;
        uint4 rawv = *(const uint4*)(vg + (size_t)r * 64 + c8);
        const __half2* hv = (const __half2*)&rawv;
#pragma unroll
        for (int j = 0; j < 4; j++) {
            float2 fv = __half22float2(hv[j]);
            sB[r * 66 + c8 + 2 * j]     = fv.x;
            sB[r * 66 + c8 + 2 * j + 1] = fv.y;
        }
    }
    __syncthreads();

    {
        const int r = tid >> 2, part = tid & 3;
        float mx = -1e30f;
#pragma unroll
        for (int j = 0; j < 16; j++) mx = fmaxf(mx, sA[r * 68 + part + 4 * j]);
        mx = fmaxf(mx, __shfl_xor_sync(0xffffffffu, mx, 1));
        mx = fmaxf(mx, __shfl_xor_sync(0xffffffffu, mx, 2));
        float sum = 0.f;
#pragma unroll
        for (int j = 0; j < 16; j++) {
            float e = expf(sA[r * 68 + part + 4 * j] - mx);
            sA[r * 68 + part + 4 * j] = e;
            sum += e;
        }
        sum += __shfl_xor_sync(0xffffffffu, sum, 1);
        sum += __shfl_xor_sync(0xffffffffu, sum, 2);
        const float inv = 1.f / sum;
#pragma unroll
        for (int j = 0; j < 16; j++) sA[r * 68 + part + 4 * j] *= inv;
    }
    __syncthreads();

    const int d = tid & 63;
    unsigned long long vreg2[32];
#pragma unroll
    for (int mm = 0; mm < 32; mm++) {
        asm("mov.b64 %0, {%1, %2};" : "=l"(vreg2[mm])
            : "f"(sB[(2 * mm) * 66 + d]), "f"(sB[(2 * mm + 1) * 66 + d]));
    }
#pragma unroll
    for (int i = 0; i < 16; i++) {
        const int n = nbase + 4 * i;
        unsigned long long acc2 = 0ULL;
        const unsigned long long* pp = (const unsigned long long*)&sA[n * 68];
#pragma unroll
        for (int m2 = 0; m2 < 32; m2++) fma2(acc2, pp[m2], vreg2[m2]);
        const float o = fma2_sum(acc2);
        g_attn2[(size_t)(wt * 64 + n) * 1024 + h * 64 + d] = __float2half_rn(o);
    }
}

// --------------------------- LN kernels --------------------------------------
__device__ __forceinline__ float2 block_reduce2(float s, float q, float* red)
{
#pragma unroll
    for (int o = 16; o; o >>= 1) {
        s += __shfl_xor_sync(0xffffffffu, s, o);
        q += __shfl_xor_sync(0xffffffffu, q, o);
    }
    const int w = threadIdx.x >> 5;
    if ((threadIdx.x & 31) == 0) { red[w] = s; red[8 + w] = q; }
    __syncthreads();
    s = red[threadIdx.x & 7];
    q = red[8 + (threadIdx.x & 7)];
#pragma unroll
    for (int o = 4; o; o >>= 1) {
        s += __shfl_xor_sync(0xffffffffu, s, o);
        q += __shfl_xor_sync(0xffffffffu, q, o);
    }
    return make_float2(s, q);
}

__global__ void __launch_bounds__(256) lnscatter_kernel(
    const float* __restrict__ x, const float* __restrict__ w,
    const float* __restrict__ b, float* __restrict__ out)
{
    __shared__ float red[16];
    const int wr = blockIdx.x;
    const int g = winmap(wr);
    const float* p = g_proj + (size_t)wr * 1024;
    float vv[4], s = 0.f, q = 0.f;
#pragma unroll
    for (int i = 0; i < 4; i++) {
        vv[i] = p[threadIdx.x + 256 * i];
        s += vv[i]; q += vv[i] * vv[i];
    }
    float2 t = block_reduce2(s, q, red);
    const float mean = t.x * (1.f / 1024.f);
    const float var = t.y * (1.f / 1024.f) - mean * mean;
    const float rs = rsqrtf(var + 1e-5f);
    const float* xr = x + (size_t)g * 1024;
    float* orow = out + (size_t)g * 1024;
    __half* drow = g_out2 + (size_t)g * 1024;
#pragma unroll
    for (int i = 0; i < 4; i++) {
        const int c = threadIdx.x + 256 * i;
        const float val = xr[c] + (vv[i] - mean) * rs * w[c] + b[c];
        orow[c] = val;
        drow[c] = __float2half_rn(val);
    }
}

__global__ void __launch_bounds__(256) lnadd_kernel(
    const float* __restrict__ w, const float* __restrict__ b,
    float* __restrict__ out)
{
    __shared__ float red[16];
    const int tok = blockIdx.x;
    const float* p = g_mlp + (size_t)tok * 1024;
    float vv[4], s = 0.f, q = 0.f;
#pragma unroll
    for (int i = 0; i < 4; i++) {
        vv[i] = p[threadIdx.x + 256 * i];
        s += vv[i]; q += vv[i] * vv[i];
    }
    float2 t = block_reduce2(s, q, red);
    const float mean = t.x * (1.f / 1024.f);
    const float var = t.y * (1.f / 1024.f) - mean * mean;
    const float rs = rsqrtf(var + 1e-5f);
    float* orow = out + (size_t)tok * 1024;
#pragma unroll
    for (int i = 0; i < 4; i++) {
        const int c = threadIdx.x + 256 * i;
        orow[c] += (vv[i] - mean) * rs * w[c] + b[c];
    }
}

// ------------------------------- launcher -----------------------------------
extern "C" void kernel_launch(void* const* d_in, const int* in_sizes, int n_in,
                              void* d_out, int out_size)
{
    const float* x      = (const float*)d_in[0];
    const float* qkv_w  = (const float*)d_in[1];
    const float* q_bias = (const float*)d_in[2];
    const float* v_bias = (const float*)d_in[3];
    const float* lscale = (const float*)d_in[4];
    const float* cpb_w1 = (const float*)d_in[5];
    const float* cpb_b1 = (const float*)d_in[6];
    const float* cpb_w2 = (const float*)d_in[7];
    const float* proj_w = (const float*)d_in[8];
    const float* proj_b = (const float*)d_in[9];
    const float* n1w    = (const float*)d_in[10];
    const float* n1b    = (const float*)d_in[11];
    const float* fc1_w  = (const float*)d_in[12];
    const float* fc1_b  = (const float*)d_in[13];
    const float* fc2_w  = (const float*)d_in[14];
    const float* fc2_b  = (const float*)d_in[15];
    const float* n2w    = (const float*)d_in[16];
    const float* n2b    = (const float*)d_in[17];
    float* out = (float*)d_out;

    __half *p_xg, *p_w2, *p_attn2, *p_out2, *p_h2;
    float *p_proj, *p_mlp;
    cudaGetSymbolAddress((void**)&p_xg,    g_xg);
    cudaGetSymbolAddress((void**)&p_w2,    g_w2);
    cudaGetSymbolAddress((void**)&p_attn2, g_attn2);
    cudaGetSymbolAddress((void**)&p_out2,  g_out2);
    cudaGetSymbolAddress((void**)&p_h2,    g_h2);
    cudaGetSymbolAddress((void**)&p_proj,  g_proj);
    cudaGetSymbolAddress((void**)&p_mlp,   g_mlp);

    const int SMEMSZ = 4 * STAGEB;  // 81920
    cudaFuncSetAttribute(mma_gemm<0>, cudaFuncAttributeMaxDynamicSharedMemorySize, SMEMSZ);
    cudaFuncSetAttribute(mma_gemm<1>, cudaFuncAttributeMaxDynamicSharedMemorySize, SMEMSZ);
    cudaFuncSetAttribute(mma_gemm<2>, cudaFuncAttributeMaxDynamicSharedMemorySize, SMEMSZ);
    cudaFuncSetAttribute(mma_gemm<3>, cudaFuncAttributeMaxDynamicSharedMemorySize, SMEMSZ);

    // order: QKV GEMM is the 4th launch (ncu capture slot)
    wconv_kernel<<<3072, 256>>>(qkv_w, p_w2 + W2_QKV, 1024);
    xconv_kernel<<<32768, 256>>>(x);
    wconv_kernel<<<4096, 256>>>(fc1_w, p_w2 + W2_FC1, 1024);

    // QKV: M=32768, N=3072, K=1024  (4th launch)
    mma_gemm<0><<<dim3(24, 256), 512, SMEMSZ>>>(
        p_xg, p_w2 + W2_QKV, q_bias, v_bias, nullptr, 1024, 3072);

    cpb_kernel<<<225, 512>>>(cpb_w1, cpb_b1, cpb_w2);
    attn_kernel<<<dim3(16, 512), 256>>>(lscale);

    wconv_kernel<<<1024, 256>>>(proj_w, p_w2 + W2_PROJ, 1024);
    // proj: N=1024, K=1024
    mma_gemm<1><<<dim3(8, 256), 512, SMEMSZ>>>(
        p_attn2, p_w2 + W2_PROJ, proj_b, nullptr, p_proj, 1024, 1024);

    lnscatter_kernel<<<32768, 256>>>(x, n1w, n1b, out);

    // fc1 + GELU: N=4096, K=1024
    mma_gemm<2><<<dim3(32, 256), 512, SMEMSZ>>>(
        p_out2, p_w2 + W2_FC1, fc1_b, nullptr, nullptr, 1024, 4096);

    wconv_kernel<<<1024, 256>>>(fc2_w, p_w2 + W2_FC2, 4096);
    // fc2: N=1024, K=4096
    mma_gemm<3><<<dim3(8, 256), 512, SMEMSZ>>>(
        p_h2, p_w2 + W2_FC2, fc2_b, nullptr, p_mlp, 4096, 1024);

    lnadd_kernel<<<32768, 256>>>(n2w, n2b, out);
}

// round 16
// speedup vs baseline: 1.1629x; 1.1629x over previous
#include <cuda_runtime.h>
#include <cuda_fp16.h>
#include <math.h>
#include <stdint.h>

// ===========================================================================
// SwinV2 block. GEMMs via mma.sync (HMMA) pure fp16 x fp16, fp32 accum.
// CTA 128x128, BK=32, 8 warps of 64x32, 4-stage cp.async, 2 CTAs/SM (R13).
// All inter-GEMM intermediates fp16 (qkv, attn, out2, h2, proj, mlp).
// Attention dots use fma.rn.f32x2 (FFMA2).
// ===========================================================================

#define LN100 4.6051701859880914f

// ------------------------- scratch (device globals) ------------------------
__device__ __align__(128) __half g_xg[33554432];     // [32768][1024] A qkv
__device__ __align__(128) __half g_w2[12582912];     // weights fp16
__device__ __align__(128) __half g_qkvh[100663296];  // [3][512][16][64][64] fp16
__device__ __align__(128) __half g_attn2[33554432];  // [32768][1024] A proj
__device__ __align__(128) __half g_out2[33554432];   // [32768][1024] A fc1
__device__ __align__(128) __half g_h2[134217728];    // [32768][4096] A fc2
__device__ __align__(128) __half g_projh[33554432];  // [32768][1024] fp16
__device__ __align__(128) __half g_mlph[33554432];   // [32768][1024] fp16
__device__ float g_tbl[3600];

#define W2_QKV  0
#define W2_PROJ 3145728
#define W2_FC1  4194304
#define W2_FC2  8388608

__device__ __forceinline__ int winmap(int wr) {
    int wt = wr >> 6, t = wr & 63;
    int img = wt >> 2, wi = wt & 3;
    int r = (((wi >> 1) << 3) + (t >> 3) + 4) & 15;
    int c = (((wi & 1) << 3) + (t & 7) + 4) & 15;
    return (img << 8) + (r << 4) + c;
}

// ---------------------------- PTX helpers -----------------------------------
__device__ __forceinline__ uint32_t smem_u32(const void* p) {
    uint32_t a;
    asm("{ .reg .u64 t; cvta.to.shared.u64 t, %1; cvt.u32.u64 %0, t; }"
        : "=r"(a) : "l"(p));
    return a;
}
__device__ __forceinline__ void cp16(uint32_t s, const void* g) {
    asm volatile("cp.async.cg.shared.global [%0], [%1], 16;" :: "r"(s), "l"(g));
}
#define CP_COMMIT() asm volatile("cp.async.commit_group;" ::: "memory")
#define CP_WAIT2()  asm volatile("cp.async.wait_group 2;" ::: "memory")

__device__ __forceinline__ void ldmx4(uint32_t a, uint32_t& r0, uint32_t& r1,
                                      uint32_t& r2, uint32_t& r3) {
    asm volatile("ldmatrix.sync.aligned.m8n8.x4.shared.b16 {%0,%1,%2,%3}, [%4];"
                 : "=r"(r0), "=r"(r1), "=r"(r2), "=r"(r3) : "r"(a));
}
__device__ __forceinline__ void mma16816(float* c, const uint32_t* a,
                                         const uint32_t* b) {
    asm volatile(
        "mma.sync.aligned.m16n8k16.row.col.f32.f16.f16.f32 "
        "{%0,%1,%2,%3}, {%4,%5,%6,%7}, {%8,%9}, {%0,%1,%2,%3};"
        : "+f"(c[0]), "+f"(c[1]), "+f"(c[2]), "+f"(c[3])
        : "r"(a[0]), "r"(a[1]), "r"(a[2]), "r"(a[3]), "r"(b[0]), "r"(b[1]));
}
__device__ __forceinline__ void fma2(unsigned long long& c,
                                     unsigned long long a, unsigned long long b) {
    asm("fma.rn.f32x2 %0, %1, %2, %0;" : "+l"(c) : "l"(a), "l"(b));
}
__device__ __forceinline__ float fma2_sum(unsigned long long c) {
    float lo, hi;
    asm("mov.b64 {%0, %1}, %2;" : "=f"(lo), "=f"(hi) : "l"(c));
    return lo + hi;
}

// ------------------------------- HMMA GEMM ----------------------------------
// C[M,N] = A[M,K] * B[N,K]^T. CTA 128x128, BK=32, 8 warps of 64x32 (R13).
// MODE 0: QKV scatter (+q/v bias) -> g_qkvh fp16
// MODE 1: +bias -> g_projh fp16
// MODE 2: +bias +exact GELU -> g_h2 fp16
// MODE 3: +bias -> g_mlph fp16
#define SPITCH 80
#define ATILE  10240           // 128*80
#define STAGEB 20480           // A + B

template <int MODE>
__global__ void __launch_bounds__(256, 2) mma_gemm(
    const __half* __restrict__ A, const __half* __restrict__ B,
    const float* __restrict__ bias, const float* __restrict__ bias2,
    __half* __restrict__ Ch, int K, int N)
{
    extern __shared__ __align__(128) char sm[];
    const uint32_t smu = smem_u32(sm);
    const int tid = threadIdx.x;
    const int lane = tid & 31, w = tid >> 5;
    const int warpM = w >> 2, warpN = w & 3;
    const int row0 = blockIdx.y * 128, col0 = blockIdx.x * 128;

    const int r1 = tid >> 2, kc = tid & 3;
    const __half* Ag0 = A + (size_t)(row0 + r1) * K + kc * 8;
    const __half* Ag1 = Ag0 + (size_t)64 * K;
    const __half* Bg0 = B + (size_t)(col0 + r1) * K + kc * 8;
    const __half* Bg1 = Bg0 + (size_t)64 * K;
    const uint32_t sd0 = (uint32_t)(r1 * SPITCH + kc * 16);
    const uint32_t sd1 = sd0 + 64 * SPITCH;

    const uint32_t aoff =
        (uint32_t)((warpM * 64 + (lane & 7) + ((lane >> 3) & 1) * 8) * SPITCH +
                   ((lane >> 4) & 1) * 16);
    const uint32_t boff =
        (uint32_t)(ATILE + (warpN * 32 + (lane & 7) + ((lane >> 4) & 1) * 8) * SPITCH +
                   ((lane >> 3) & 1) * 16);

    float acc[16][4];
#pragma unroll
    for (int i = 0; i < 16; i++)
#pragma unroll
        for (int j = 0; j < 4; j++) acc[i][j] = 0.f;

    const int T = K >> 5;

    // prologue: stages 0,1,2
#pragma unroll
    for (int s = 0; s < 3; s++) {
        const uint32_t sb = smu + s * STAGEB;
        const size_t ko = (size_t)s * 32;
        cp16(sb + sd0, Ag0 + ko);
        cp16(sb + sd1, Ag1 + ko);
        cp16(sb + ATILE + sd0, Bg0 + ko);
        cp16(sb + ATILE + sd1, Bg1 + ko);
        CP_COMMIT();
    }

    for (int kt = 0; kt < T; ++kt) {
        CP_WAIT2();
        __syncthreads();

        if (kt + 3 < T) {
            const uint32_t sb = smu + ((kt + 3) & 3) * STAGEB;
            const size_t ko = (size_t)(kt + 3) * 32;
            cp16(sb + sd0, Ag0 + ko);
            cp16(sb + sd1, Ag1 + ko);
            cp16(sb + ATILE + sd0, Bg0 + ko);
            cp16(sb + ATILE + sd1, Bg1 + ko);
        }
        CP_COMMIT();

        const uint32_t base = smu + (kt & 3) * STAGEB;
#pragma unroll
        for (int kk = 0; kk < 2; kk++) {
            uint32_t bf[4][2];
#pragma unroll
            for (int p = 0; p < 2; p++)
                ldmx4(base + boff + p * 16 * SPITCH + kk * 32,
                      bf[2 * p][0], bf[2 * p][1], bf[2 * p + 1][0], bf[2 * p + 1][1]);
#pragma unroll
            for (int mt = 0; mt < 4; mt++) {
                uint32_t af[4];
                ldmx4(base + aoff + mt * 16 * SPITCH + kk * 32,
                      af[0], af[1], af[2], af[3]);
#pragma unroll
                for (int nt = 0; nt < 4; nt++)
                    mma16816(acc[mt * 4 + nt], af, bf[nt]);
            }
        }
    }

    // ------------------------------ epilogue --------------------------------
#pragma unroll
    for (int mt = 0; mt < 4; mt++) {
#pragma unroll
        for (int nt = 0; nt < 4; nt++) {
            const float* c = acc[mt * 4 + nt];
            const int col = col0 + warpN * 32 + nt * 8 + (lane & 3) * 2;
#pragma unroll
            for (int half = 0; half < 2; half++) {
                const int row = row0 + warpM * 64 + mt * 16 + (lane >> 2) + half * 8;
                const float v0 = c[half * 2 + 0], v1 = c[half * 2 + 1];
                if (MODE == 0) {
                    const int which = col >> 10, rem = col & 1023;
                    const float* bs = (which == 0) ? bias : (which == 2) ? bias2 : nullptr;
                    const float b0 = bs ? bs[rem] : 0.f, b1 = bs ? bs[rem + 1] : 0.f;
                    __half* dst = g_qkvh + (size_t)which * 33554432 +
                                  (size_t)(row >> 6) * 65536 + (rem >> 6) * 4096 +
                                  (row & 63) * 64 + (rem & 63);
                    __half2 hh;
                    hh.x = __float2half_rn(v0 + b0);
                    hh.y = __float2half_rn(v1 + b1);
                    *(__half2*)dst = hh;
                } else if (MODE == 2) {
                    float s0 = v0 + bias[col], s1 = v1 + bias[col + 1];
                    s0 = 0.5f * s0 * (1.0f + erff(s0 * 0.70710678118654752f));
                    s1 = 0.5f * s1 * (1.0f + erff(s1 * 0.70710678118654752f));
                    __half2 hh;
                    hh.x = __float2half_rn(s0);
                    hh.y = __float2half_rn(s1);
                    *(__half2*)(g_h2 + (size_t)row * 4096 + col) = hh;
                } else {
                    __half2 hh;
                    hh.x = __float2half_rn(v0 + bias[col]);
                    hh.y = __float2half_rn(v1 + bias[col + 1]);
                    *(__half2*)(Ch + (size_t)row * N + col) = hh;
                }
            }
        }
    }
}

// ------------------------- convert / gather kernels --------------------------
__global__ void __launch_bounds__(256) xconv_kernel(const float* __restrict__ x)
{
    const int wr = blockIdx.x;
    const int g = winmap(wr);
    const float4 v = *(const float4*)(x + (size_t)g * 1024 + threadIdx.x * 4);
    __half2 h01, h23;
    h01.x = __float2half_rn(v.x); h01.y = __float2half_rn(v.y);
    h23.x = __float2half_rn(v.z); h23.y = __float2half_rn(v.w);
    __half* dst = g_xg + (size_t)wr * 1024 + threadIdx.x * 4;
    *(__half2*)(dst) = h01;
    *(__half2*)(dst + 2) = h23;
}

__global__ void __launch_bounds__(256) wconv_kernel(
    const float* __restrict__ src, __half* __restrict__ dst, int K)
{
    const int row = blockIdx.x;
    const float* s = src + (size_t)row * K;
    __half* d = dst + (size_t)row * K;
    for (int c = threadIdx.x * 4; c < K; c += 1024) {
        const float4 v = *(const float4*)(s + c);
        __half2 h01, h23;
        h01.x = __float2half_rn(v.x); h01.y = __float2half_rn(v.y);
        h23.x = __float2half_rn(v.z); h23.y = __float2half_rn(v.w);
        *(__half2*)(d + c) = h01;
        *(__half2*)(d + c + 2) = h23;
    }
}

// --------------------------- CPB bias table ---------------------------------
__global__ void cpb_kernel(const float* __restrict__ w1,
                           const float* __restrict__ b1,
                           const float* __restrict__ w2)
{
    __shared__ float hbuf[512];
    const int p = blockIdx.x;
    const int a = p / 15, b = p % 15;
    const float va = (a - 7) * (1.0f / 7.0f), vb = (b - 7) * (1.0f / 7.0f);
    const float c0 = (va > 0.f ? 1.f : (va < 0.f ? -1.f : 0.f)) * log2f(1.f + fabsf(va));
    const float c1 = (vb > 0.f ? 1.f : (vb < 0.f ? -1.f : 0.f)) * log2f(1.f + fabsf(vb));
    const int j = threadIdx.x;
    float hv = w1[j * 2] * c0 + w1[j * 2 + 1] * c1 + b1[j];
    hbuf[j] = fmaxf(hv, 0.f);
    __syncthreads();
    if (j < 16) {
        float s = 0.f;
        for (int t = 0; t < 512; t++) s += hbuf[t] * w2[j * 512 + t];
        g_tbl[p * 16 + j] = 16.f / (1.f + expf(-s));
    }
}

// ------------------------------ attention -----------------------------------
__global__ void __launch_bounds__(256) attn_kernel(const float* __restrict__ ls)
{
    __shared__ float sA[64 * 68];
    __shared__ float sB[64 * 66];
    __shared__ float rn[128];

    const int h = blockIdx.x, wt = blockIdx.y;
    const int tid = threadIdx.x;
    const __half* qg = g_qkvh + (size_t)wt * 65536 + h * 4096;
    const __half* kg = qg + 33554432;
    const __half* vg = qg + 67108864;

#pragma unroll
    for (int i = 0; i < 2; i++) {
        const int idx = tid + 256 * i;
        const int r = idx >> 3, c8 = (idx & 7) * 8;
        uint4 rawq = *(const uint4*)(qg + (size_t)r * 64 + c8);
        uint4 rawk = *(const uint4*)(kg + (size_t)r * 64 + c8);
        const __half2* hq = (const __half2*)&rawq;
        const __half2* hk = (const __half2*)&rawk;
#pragma unroll
        for (int j = 0; j < 4; j++) {
            float2 fq = __half22float2(hq[j]);
            float2 fk = __half22float2(hk[j]);
            sA[r * 68 + c8 + 2 * j]     = fq.x;
            sA[r * 68 + c8 + 2 * j + 1] = fq.y;
            sB[r * 66 + c8 + 2 * j]     = fk.x;
            sB[r * 66 + c8 + 2 * j + 1] = fk.y;
        }
    }
    __syncthreads();

    {
        const int r = tid >> 2, part = tid & 3;
        float sq = 0.f, sk = 0.f;
#pragma unroll
        for (int j = 0; j < 16; j++) {
            float xq = sA[r * 68 + part + 4 * j]; sq += xq * xq;
            float xk = sB[r * 66 + part + 4 * j]; sk += xk * xk;
        }
        sq += __shfl_xor_sync(0xffffffffu, sq, 1);
        sq += __shfl_xor_sync(0xffffffffu, sq, 2);
        sk += __shfl_xor_sync(0xffffffffu, sk, 1);
        sk += __shfl_xor_sync(0xffffffffu, sk, 2);
        if (part == 0) {
            rn[r]      = 1.f / fmaxf(sqrtf(sq), 1e-12f);
            rn[64 + r] = 1.f / fmaxf(sqrtf(sk), 1e-12f);
        }
    }
    __syncthreads();

    const float scale = expf(fminf(ls[h], LN100));
    const int wi = wt & 3;
    const int m = tid & 63;
    const int nbase = tid >> 6;

    unsigned long long kreg2[32];
#pragma unroll
    for (int kk = 0; kk < 32; kk++)
        kreg2[kk] = *(const unsigned long long*)&sB[m * 66 + 2 * kk];

    const int srm = ((wi >> 1) << 3) + (m >> 3), scm = ((wi & 1) << 3) + (m & 7);
    const int rgm = (srm < 8 ? 0 : (srm < 12 ? 1 : 2)) * 3 +
                    (scm < 8 ? 0 : (scm < 12 ? 1 : 2));

    float sc[16];
#pragma unroll
    for (int i = 0; i < 16; i++) {
        const int n = nbase + 4 * i;
        unsigned long long acc2 = 0ULL;
        const unsigned long long* qp = (const unsigned long long*)&sA[n * 68];
#pragma unroll
        for (int k2 = 0; k2 < 32; k2++) fma2(acc2, qp[k2], kreg2[k2]);
        float dot = fma2_sum(acc2);
        dot *= rn[n] * rn[64 + m] * scale;
        const int idx = ((n >> 3) - (m >> 3) + 7) * 15 + ((n & 7) - (m & 7) + 7);
        dot += g_tbl[idx * 16 + h];
        const int srn = ((wi >> 1) << 3) + (n >> 3), scn = ((wi & 1) << 3) + (n & 7);
        const int rgn = (srn < 8 ? 0 : (srn < 12 ? 1 : 2)) * 3 +
                        (scn < 8 ? 0 : (scn < 12 ? 1 : 2));
        if (rgn != rgm) dot -= 100.f;
        sc[i] = dot;
    }
    __syncthreads();

#pragma unroll
    for (int i = 0; i < 16; i++) sA[(nbase + 4 * i) * 68 + m] = sc[i];
#pragma unroll
    for (int i = 0; i < 2; i++) {
        const int idx = tid + 256 * i;
        const int r = idx >> 3, c8 = (idx & 7) * 8;
        uint4 rawv = *(const uint4*)(vg + (size_t)r * 64 + c8);
        const __half2* hv = (const __half2*)&rawv;
#pragma unroll
        for (int j = 0; j < 4; j++) {
            float2 fv = __half22float2(hv[j]);
            sB[r * 66 + c8 + 2 * j]     = fv.x;
            sB[r * 66 + c8 + 2 * j + 1] = fv.y;
        }
    }
    __syncthreads();

    {
        const int r = tid >> 2, part = tid & 3;
        float mx = -1e30f;
#pragma unroll
        for (int j = 0; j < 16; j++) mx = fmaxf(mx, sA[r * 68 + part + 4 * j]);
        mx = fmaxf(mx, __shfl_xor_sync(0xffffffffu, mx, 1));
        mx = fmaxf(mx, __shfl_xor_sync(0xffffffffu, mx, 2));
        float sum = 0.f;
#pragma unroll
        for (int j = 0; j < 16; j++) {
            float e = expf(sA[r * 68 + part + 4 * j] - mx);
            sA[r * 68 + part + 4 * j] = e;
            sum += e;
        }
        sum += __shfl_xor_sync(0xffffffffu, sum, 1);
        sum += __shfl_xor_sync(0xffffffffu, sum, 2);
        const float inv = 1.f / sum;
#pragma unroll
        for (int j = 0; j < 16; j++) sA[r * 68 + part + 4 * j] *= inv;
    }
    __syncthreads();

    const int d = tid & 63;
    unsigned long long vreg2[32];
#pragma unroll
    for (int mm = 0; mm < 32; mm++) {
        asm("mov.b64 %0, {%1, %2};" : "=l"(vreg2[mm])
            : "f"(sB[(2 * mm) * 66 + d]), "f"(sB[(2 * mm + 1) * 66 + d]));
    }
#pragma unroll
    for (int i = 0; i < 16; i++) {
        const int n = nbase + 4 * i;
        unsigned long long acc2 = 0ULL;
        const unsigned long long* pp = (const unsigned long long*)&sA[n * 68];
#pragma unroll
        for (int m2 = 0; m2 < 32; m2++) fma2(acc2, pp[m2], vreg2[m2]);
        const float o = fma2_sum(acc2);
        g_attn2[(size_t)(wt * 64 + n) * 1024 + h * 64 + d] = __float2half_rn(o);
    }
}

// --------------------------- LN kernels --------------------------------------
__device__ __forceinline__ float2 block_reduce2(float s, float q, float* red)
{
#pragma unroll
    for (int o = 16; o; o >>= 1) {
        s += __shfl_xor_sync(0xffffffffu, s, o);
        q += __shfl_xor_sync(0xffffffffu, q, o);
    }
    const int w = threadIdx.x >> 5;
    if ((threadIdx.x & 31) == 0) { red[w] = s; red[8 + w] = q; }
    __syncthreads();
    s = red[threadIdx.x & 7];
    q = red[8 + (threadIdx.x & 7)];
#pragma unroll
    for (int o = 4; o; o >>= 1) {
        s += __shfl_xor_sync(0xffffffffu, s, o);
        q += __shfl_xor_sync(0xffffffffu, q, o);
    }
    return make_float2(s, q);
}

// xs1[g] = x[g] + LN(projh[wr]); also emits fp16 rows for fc1 A
__global__ void __launch_bounds__(256) lnscatter_kernel(
    const float* __restrict__ x, const float* __restrict__ w,
    const float* __restrict__ b, float* __restrict__ out)
{
    __shared__ float red[16];
    const int wr = blockIdx.x;
    const int g = winmap(wr);
    const __half* p = g_projh + (size_t)wr * 1024;
    float vv[4], s = 0.f, q = 0.f;
#pragma unroll
    for (int i = 0; i < 2; i++) {
        const __half2 h2v = *(const __half2*)(p + threadIdx.x * 2 + 512 * i);
        const float2 f = __half22float2(h2v);
        vv[2 * i] = f.x; vv[2 * i + 1] = f.y;
        s += f.x + f.y; q += f.x * f.x + f.y * f.y;
    }
    float2 t = block_reduce2(s, q, red);
    const float mean = t.x * (1.f / 1024.f);
    const float var = t.y * (1.f / 1024.f) - mean * mean;
    const float rs = rsqrtf(var + 1e-5f);
    const float* xr = x + (size_t)g * 1024;
    float* orow = out + (size_t)g * 1024;
    __half* drow = g_out2 + (size_t)g * 1024;
#pragma unroll
    for (int i = 0; i < 4; i++) {
        const int c = threadIdx.x * 2 + (i >> 1) * 512 + (i & 1);
        const float val = xr[c] + (vv[i] - mean) * rs * w[c] + b[c];
        orow[c] = val;
        drow[c] = __float2half_rn(val);
    }
}

// out[tok] += LN(mlph[tok])
__global__ void __launch_bounds__(256) lnadd_kernel(
    const float* __restrict__ w, const float* __restrict__ b,
    float* __restrict__ out)
{
    __shared__ float red[16];
    const int tok = blockIdx.x;
    const __half* p = g_mlph + (size_t)tok * 1024;
    float vv[4], s = 0.f, q = 0.f;
#pragma unroll
    for (int i = 0; i < 2; i++) {
        const __half2 h2v = *(const __half2*)(p + threadIdx.x * 2 + 512 * i);
        const float2 f = __half22float2(h2v);
        vv[2 * i] = f.x; vv[2 * i + 1] = f.y;
        s += f.x + f.y; q += f.x * f.x + f.y * f.y;
    }
    float2 t = block_reduce2(s, q, red);
    const float mean = t.x * (1.f / 1024.f);
    const float var = t.y * (1.f / 1024.f) - mean * mean;
    const float rs = rsqrtf(var + 1e-5f);
    float* orow = out + (size_t)tok * 1024;
#pragma unroll
    for (int i = 0; i < 4; i++) {
        const int c = threadIdx.x * 2 + (i >> 1) * 512 + (i & 1);
        orow[c] += (vv[i] - mean) * rs * w[c] + b[c];
    }
}

// ------------------------------- launcher -----------------------------------
extern "C" void kernel_launch(void* const* d_in, const int* in_sizes, int n_in,
                              void* d_out, int out_size)
{
    const float* x      = (const float*)d_in[0];
    const float* qkv_w  = (const float*)d_in[1];
    const float* q_bias = (const float*)d_in[2];
    const float* v_bias = (const float*)d_in[3];
    const float* lscale = (const float*)d_in[4];
    const float* cpb_w1 = (const float*)d_in[5];
    const float* cpb_b1 = (const float*)d_in[6];
    const float* cpb_w2 = (const float*)d_in[7];
    const float* proj_w = (const float*)d_in[8];
    const float* proj_b = (const float*)d_in[9];
    const float* n1w    = (const float*)d_in[10];
    const float* n1b    = (const float*)d_in[11];
    const float* fc1_w  = (const float*)d_in[12];
    const float* fc1_b  = (const float*)d_in[13];
    const float* fc2_w  = (const float*)d_in[14];
    const float* fc2_b  = (const float*)d_in[15];
    const float* n2w    = (const float*)d_in[16];
    const float* n2b    = (const float*)d_in[17];
    float* out = (float*)d_out;

    __half *p_xg, *p_w2, *p_attn2, *p_out2, *p_h2, *p_projh, *p_mlph;
    cudaGetSymbolAddress((void**)&p_xg,    g_xg);
    cudaGetSymbolAddress((void**)&p_w2,    g_w2);
    cudaGetSymbolAddress((void**)&p_attn2, g_attn2);
    cudaGetSymbolAddress((void**)&p_out2,  g_out2);
    cudaGetSymbolAddress((void**)&p_h2,    g_h2);
    cudaGetSymbolAddress((void**)&p_projh, g_projh);
    cudaGetSymbolAddress((void**)&p_mlph,  g_mlph);

    const int SMEMSZ = 4 * STAGEB;  // 81920
    cudaFuncSetAttribute(mma_gemm<0>, cudaFuncAttributeMaxDynamicSharedMemorySize, SMEMSZ);
    cudaFuncSetAttribute(mma_gemm<1>, cudaFuncAttributeMaxDynamicSharedMemorySize, SMEMSZ);
    cudaFuncSetAttribute(mma_gemm<2>, cudaFuncAttributeMaxDynamicSharedMemorySize, SMEMSZ);
    cudaFuncSetAttribute(mma_gemm<3>, cudaFuncAttributeMaxDynamicSharedMemorySize, SMEMSZ);

    // order: QKV GEMM is the 4th launch (ncu capture slot)
    wconv_kernel<<<3072, 256>>>(qkv_w, p_w2 + W2_QKV, 1024);
    xconv_kernel<<<32768, 256>>>(x);
    wconv_kernel<<<4096, 256>>>(fc1_w, p_w2 + W2_FC1, 1024);

    // QKV: M=32768, N=3072, K=1024  (4th launch)
    mma_gemm<0><<<dim3(24, 256), 256, SMEMSZ>>>(
        p_xg, p_w2 + W2_QKV, q_bias, v_bias, nullptr, 1024, 3072);

    cpb_kernel<<<225, 512>>>(cpb_w1, cpb_b1, cpb_w2);
    attn_kernel<<<dim3(16, 512), 256>>>(lscale);

    wconv_kernel<<<1024, 256>>>(proj_w, p_w2 + W2_PROJ, 1024);
    // proj: N=1024, K=1024 -> fp16
    mma_gemm<1><<<dim3(8, 256), 256, SMEMSZ>>>(
        p_attn2, p_w2 + W2_PROJ, proj_b, nullptr, p_projh, 1024, 1024);

    lnscatter_kernel<<<32768, 256>>>(x, n1w, n1b, out);

    // fc1 + GELU: N=4096, K=1024
    mma_gemm<2><<<dim3(32, 256), 256, SMEMSZ>>>(
        p_out2, p_w2 + W2_FC1, fc1_b, nullptr, nullptr, 1024, 4096);

    wconv_kernel<<<1024, 256>>>(fc2_w, p_w2 + W2_FC2, 4096);
    // fc2: N=1024, K=4096 -> fp16
    mma_gemm<3><<<dim3(8, 256), 256, SMEMSZ>>>(
        p_h2, p_w2 + W2_FC2, fc2_b, nullptr, p_mlph, 4096, 1024);

    lnadd_kernel<<<32768, 256>>>(n2w, n2b, out);
}